// round 5
// baseline (speedup 1.0000x reference)
#include <cuda_runtime.h>
#include <cuda_bf16.h>
#include <math.h>
#include <stdint.h>

#define NN 4096
#define DD 256
#define HH 8
#define HDIM 32
#define ROWCAP 256
#define EPS 1e-5f
#define FFD 512

// ---------------- static scratch ----------------
__device__ int   g_cols[NN * ROWCAP];
__device__ float g_avals[NN * ROWCAP];
__device__ int   g_nnz[NN];
__device__ float g_Q[NN * DD];     // permuted [n][head*32+hd], pre-scaled
__device__ float g_K[NN * DD];
__device__ float g_V[NN * DD];
__device__ float g_attn[NN * DD];
__device__ float g_x1[NN * DD];
__device__ float g_bn1[NN * DD];
__device__ float g_mid[NN * FFD];
__device__ float g_x2[NN * DD];
__device__ float g_stats[1280];

// ================= helpers =================
__device__ __forceinline__ uint32_t smem_u32(const void* p) {
    uint32_t a;
    asm("{ .reg .u64 t; cvta.to.shared.u64 t, %1; cvt.u32.u64 %0, t; }" : "=r"(a) : "l"(p));
    return a;
}

__device__ __forceinline__ void ldm4(uint32_t addr, uint32_t& r0, uint32_t& r1,
                                     uint32_t& r2, uint32_t& r3) {
    asm volatile("ldmatrix.sync.aligned.m8n8.x4.shared.b16 {%0,%1,%2,%3}, [%4];"
                 : "=r"(r0), "=r"(r1), "=r"(r2), "=r"(r3) : "r"(addr));
}

__device__ __forceinline__ void mma16816(float* c, uint32_t a0, uint32_t a1,
                                         uint32_t a2, uint32_t a3,
                                         uint32_t b0, uint32_t b1) {
    asm volatile(
        "mma.sync.aligned.m16n8k16.row.col.f32.bf16.bf16.f32 "
        "{%0,%1,%2,%3}, {%4,%5,%6,%7}, {%8,%9}, {%0,%1,%2,%3};"
        : "+f"(c[0]), "+f"(c[1]), "+f"(c[2]), "+f"(c[3])
        : "r"(a0), "r"(a1), "r"(a2), "r"(a3), "r"(b0), "r"(b1));
}

__device__ __forceinline__ void splitf(float x, uint32_t& h, uint32_t& l) {
    __nv_bfloat16 hb = __float2bfloat16_rn(x);
    float hf = __bfloat162float(hb);
    __nv_bfloat16 lb = __float2bfloat16_rn(x - hf);
    h = (uint32_t)__bfloat16_as_ushort(hb);
    l = (uint32_t)__bfloat16_as_ushort(lb);
}

// pair (a,b) -> 3 packed words
// A pattern per float: [hi, lo, hi]  -> w0=(hA,lA) w1=(hA,hB) w2=(lB,hB)
__device__ __forceinline__ void packA(float a, float b, uint32_t* w) {
    uint32_t ha, la, hb, lb;
    splitf(a, ha, la); splitf(b, hb, lb);
    w[0] = ha | (la << 16);
    w[1] = ha | (hb << 16);
    w[2] = lb | (hb << 16);
}
// B pattern per float: [hi, hi, lo]  -> w0=(hA,hA) w1=(lA,hB) w2=(hB,lB)
__device__ __forceinline__ void packB(float a, float b, uint32_t* w) {
    uint32_t ha, la, hb, lb;
    splitf(a, ha, la); splitf(b, hb, lb);
    w[0] = ha | (ha << 16);
    w[1] = la | (hb << 16);
    w[2] = hb | (lb << 16);
}

// ================= 3xBF16 tensor-core GEMM =================
// Y[M,Nc] = X[M,K] @ W[Nc,K]^T
// block tile 128x64, warp tile 64x16 (2x4 warps), 16 floats of K per iter
// each float expands to 3 bf16 (A:[hi,lo,hi], B:[hi,hi,lo]) -> 48 bf16 = 96B/row
// row stride 144B => ldmatrix 16B-group = (row+chunk)%8, conflict-free
// mode 0: plain  1: head-permute + scale  2: relu  3: +residual
#define BM 128
#define BN 64
#define BKF 16
#define RSTRIDE 144
#define ABYTES (128 * RSTRIDE)          // 18432
#define BUFB (ABYTES + 64 * RSTRIDE)    // 27648
#define GEMM_SMEM (2 * BUFB)            // 55296

__device__ __forceinline__ void gemm_mma_body(
    const float* __restrict__ X, const float* __restrict__ W,
    float* __restrict__ Y, int K, int Nc,
    int mode, const float* __restrict__ res, float scale)
{
    extern __shared__ __align__(16) char sm[];
    uint32_t smb = smem_u32(sm);

    int tid = threadIdx.x;
    int lane = tid & 31;
    int wid = tid >> 5;
    int wm = wid >> 2;           // 0..1 -> m offset *64
    int wn = wid & 3;            // 0..3 -> n offset *16
    int m0 = blockIdx.y * BM;
    int n0 = blockIdx.x * BN;

    // ---- load assignment: A: tid -> (row=tid>>1, t=tid&1), 8 floats each
    //                       B: tid<128 -> (row=tid>>1, t=tid&1)
    int rowA = tid >> 1;
    int tA = tid & 1;
    int rowB = (tid < 128) ? (tid >> 1) : 0;
    int tB = tid & 1;

    const float* Xp = X + (size_t)(m0 + rowA) * K + tA * 8;
    const float* Wp = W + (size_t)(n0 + rowB) * K + tB * 8;

    float4 xa[2], wb[2];
    xa[0] = *(const float4*)&Xp[0];
    xa[1] = *(const float4*)&Xp[4];
    if (tid < 128) { wb[0] = *(const float4*)&Wp[0]; wb[1] = *(const float4*)&Wp[4]; }

    uint32_t stA = (uint32_t)(rowA * RSTRIDE + tA * 48);
    uint32_t stB = (uint32_t)(ABYTES + rowB * RSTRIDE + tB * 48);

    // ---- ldmatrix per-lane constants
    int la = lane & 15;
    int kha = (lane >> 4) & 1;
    int rb = (lane & 7) + (((lane >> 4) & 1) << 3);
    int khb = (lane >> 3) & 1;

    uint32_t aRow[4];
#pragma unroll
    for (int mt = 0; mt < 4; mt++)
        aRow[mt] = (uint32_t)((wm * 64 + mt * 16 + la) * RSTRIDE);
    uint32_t bRow = (uint32_t)(ABYTES + (wn * 16 + rb) * RSTRIDE);

    float acc[4][2][4] = {};
    int nit = K / BKF;

    for (int it = 0; it < nit; it++) {
        uint32_t bufo = (uint32_t)((it & 1) * BUFB);
        // convert + store current registers
        {
            uint32_t w[12];
            float f[8] = {xa[0].x, xa[0].y, xa[0].z, xa[0].w,
                          xa[1].x, xa[1].y, xa[1].z, xa[1].w};
#pragma unroll
            for (int p = 0; p < 4; p++) packA(f[2 * p], f[2 * p + 1], w + 3 * p);
            *(uint4*)(sm + bufo + stA +  0) = make_uint4(w[0], w[1], w[2], w[3]);
            *(uint4*)(sm + bufo + stA + 16) = make_uint4(w[4], w[5], w[6], w[7]);
            *(uint4*)(sm + bufo + stA + 32) = make_uint4(w[8], w[9], w[10], w[11]);
        }
        if (tid < 128) {
            uint32_t w[12];
            float f[8] = {wb[0].x, wb[0].y, wb[0].z, wb[0].w,
                          wb[1].x, wb[1].y, wb[1].z, wb[1].w};
#pragma unroll
            for (int p = 0; p < 4; p++) packB(f[2 * p], f[2 * p + 1], w + 3 * p);
            *(uint4*)(sm + bufo + stB +  0) = make_uint4(w[0], w[1], w[2], w[3]);
            *(uint4*)(sm + bufo + stB + 16) = make_uint4(w[4], w[5], w[6], w[7]);
            *(uint4*)(sm + bufo + stB + 32) = make_uint4(w[8], w[9], w[10], w[11]);
        }
        __syncthreads();
        // prefetch next chunk
        if (it + 1 < nit) {
            int k0 = (it + 1) * BKF;
            xa[0] = *(const float4*)&Xp[k0];
            xa[1] = *(const float4*)&Xp[k0 + 4];
            if (tid < 128) {
                wb[0] = *(const float4*)&Wp[k0];
                wb[1] = *(const float4*)&Wp[k0 + 4];
            }
        }
        // compute: 3 k-steps of 16 bf16
        uint32_t sA = smb + bufo;
        uint32_t sB = smb + bufo;
#pragma unroll
        for (int ks = 0; ks < 3; ks++) {
            uint32_t b0, b1, b2, b3;
            ldm4(sB + bRow + (uint32_t)(2 * ks + khb) * 16, b0, b1, b2, b3);
            uint32_t a[4][4];
#pragma unroll
            for (int mt = 0; mt < 4; mt++)
                ldm4(sA + aRow[mt] + (uint32_t)(2 * ks + kha) * 16,
                     a[mt][0], a[mt][1], a[mt][2], a[mt][3]);
#pragma unroll
            for (int mt = 0; mt < 4; mt++) {
                mma16816(acc[mt][0], a[mt][0], a[mt][1], a[mt][2], a[mt][3], b0, b1);
                mma16816(acc[mt][1], a[mt][0], a[mt][1], a[mt][2], a[mt][3], b2, b3);
            }
        }
    }

    // ---- epilogue straight from registers
    int gid = lane >> 2, tig = lane & 3;
#pragma unroll
    for (int mt = 0; mt < 4; mt++) {
#pragma unroll
        for (int nt = 0; nt < 2; nt++) {
            int col = n0 + wn * 16 + nt * 8 + 2 * tig;
#pragma unroll
            for (int half = 0; half < 2; half++) {
                int m = m0 + wm * 64 + mt * 16 + gid + half * 8;
                size_t rowoff = (size_t)m * Nc;
                float v0 = acc[mt][nt][half * 2 + 0];
                float v1 = acc[mt][nt][half * 2 + 1];
                if (mode == 1) {
                    int p0 = (col & 7) * HDIM + (col >> 3);
                    int p1 = ((col + 1) & 7) * HDIM + ((col + 1) >> 3);
                    Y[rowoff + p0] = v0 * scale;
                    Y[rowoff + p1] = v1 * scale;
                } else if (mode == 2) {
                    *(float2*)&Y[rowoff + col] =
                        make_float2(fmaxf(v0, 0.f), fmaxf(v1, 0.f));
                } else if (mode == 3) {
                    float2 r = *(const float2*)&res[rowoff + col];
                    *(float2*)&Y[rowoff + col] = make_float2(v0 + r.x, v1 + r.y);
                } else {
                    *(float2*)&Y[rowoff + col] = make_float2(v0, v1);
                }
            }
        }
    }
}

__global__ void __launch_bounds__(256) qkv_gemm_mma(
    const float* __restrict__ X, const float* __restrict__ Wq,
    const float* __restrict__ Wk, const float* __restrict__ Wv)
{
    int z = blockIdx.z;
    const float* W = (z == 0) ? Wq : ((z == 1) ? Wk : Wv);
    float* Y = (z == 0) ? g_Q : ((z == 1) ? g_K : g_V);
    float scale = (z == 0) ? 0.0625f : 1.0f;
    gemm_mma_body(X, W, Y, DD, DD, 1, nullptr, scale);
}

__global__ void __launch_bounds__(256) gemm_mma(
    const float* __restrict__ X, const float* __restrict__ W,
    float* __restrict__ Y, int K, int Nc, int mode, const float* __restrict__ res)
{
    gemm_mma_body(X, W, Y, K, Nc, mode, res, 1.0f);
}

// ================= CSR build =================
__global__ void __launch_bounds__(256) csr_build(const float* __restrict__ A) {
    int row = blockIdx.x;
    __shared__ int cnt;
    if (threadIdx.x == 0) cnt = 0;
    __syncthreads();
    const float4* Ar = (const float4*)(A + (size_t)row * NN);
    for (int c4 = threadIdx.x; c4 < NN / 4; c4 += 256) {
        float4 a4 = Ar[c4];
        float vals[4] = {a4.x, a4.y, a4.z, a4.w};
#pragma unroll
        for (int j = 0; j < 4; j++) {
            if (vals[j] != 0.0f) {
                int p = atomicAdd(&cnt, 1);
                if (p < ROWCAP) {
                    g_cols[row * ROWCAP + p] = c4 * 4 + j;
                    g_avals[row * ROWCAP + p] = vals[j];
                }
            }
        }
    }
    __syncthreads();
    if (threadIdx.x == 0) g_nnz[row] = (cnt < ROWCAP) ? cnt : ROWCAP;
}

// ================= small kernels =================
__global__ void zero_stats() { g_stats[blockIdx.x * 256 + threadIdx.x] = 0.0f; }

__global__ void __launch_bounds__(256) colsum_v() {
    float s = 0.0f;
    int c = threadIdx.x;
    int r0 = blockIdx.x * 64;
    for (int r = r0; r < r0 + 64; r++) s += g_V[(size_t)r * DD + c];
    atomicAdd(&g_stats[c], s);
}

__global__ void __launch_bounds__(256) attn_sparse(float* __restrict__ out) {
    int n = blockIdx.x;
    int w = threadIdx.x >> 5;
    int lane = threadIdx.x & 31;
    int base = w * HDIM + lane;

    float q = g_Q[(size_t)n * DD + base];
    float acc = g_stats[base];
    int nnz = g_nnz[n];
    float z = (float)(NN - nnz);
    const int*   cols = g_cols  + (size_t)n * ROWCAP;
    const float* av   = g_avals + (size_t)n * ROWCAP;

    int i = 0;
    for (; i + 2 <= nnz; i += 2) {
        int m1 = cols[i], m2 = cols[i + 1];
        float a1 = av[i], a2 = av[i + 1];
        float k1 = g_K[(size_t)m1 * DD + base];
        float k2 = g_K[(size_t)m2 * DD + base];
        float v1 = g_V[(size_t)m1 * DD + base];
        float v2 = g_V[(size_t)m2 * DD + base];
        float s1 = q * k1, s2 = q * k2;
#pragma unroll
        for (int off = 16; off; off >>= 1) {
            s1 += __shfl_xor_sync(0xffffffffu, s1, off);
            s2 += __shfl_xor_sync(0xffffffffu, s2, off);
        }
        float e1 = __expf(a1 * s1);
        float e2 = __expf(a2 * s2);
        z += e1 + e2;
        acc += (e1 - 1.0f) * v1 + (e2 - 1.0f) * v2;
    }
    if (i < nnz) {
        int m1 = cols[i];
        float a1 = av[i];
        float s1 = q * g_K[(size_t)m1 * DD + base];
#pragma unroll
        for (int off = 16; off; off >>= 1)
            s1 += __shfl_xor_sync(0xffffffffu, s1, off);
        float e1 = __expf(a1 * s1);
        z += e1;
        acc += (e1 - 1.0f) * g_V[(size_t)m1 * DD + base];
    }
    out[(size_t)n * DD + lane * HH + w] = acc / z;
}

__global__ void __launch_bounds__(256) bn_stats(
    const float* __restrict__ X, float* __restrict__ sums, float* __restrict__ sqs)
{
    float s = 0.0f, q = 0.0f;
    int c = threadIdx.x;
    int r0 = blockIdx.x * 64;
    for (int r = r0; r < r0 + 64; r++) {
        float x = X[(size_t)r * DD + c];
        s += x; q += x * x;
    }
    atomicAdd(&sums[c], s);
    atomicAdd(&sqs[c], q);
}

__global__ void __launch_bounds__(256) bn_apply(
    const float* __restrict__ X, const float* __restrict__ sums,
    const float* __restrict__ sqs, const float* __restrict__ g,
    const float* __restrict__ b, float* __restrict__ Y)
{
    int c = threadIdx.x;
    size_t idx = (size_t)blockIdx.x * DD + c;
    float m = sums[c] * (1.0f / NN);
    float v = sqs[c] * (1.0f / NN) - m * m;
    Y[idx] = (X[idx] - m) * rsqrtf(v + EPS) * g[c] + b[c];
}

// ================= launch =================
extern "C" void kernel_launch(void* const* d_in, const int* in_sizes, int n_in,
                              void* d_out, int out_size)
{
    const float* A  = (const float*)d_in[0];
    const float* h  = (const float*)d_in[1];
    const float* Wq = (const float*)d_in[2];
    const float* Wk = (const float*)d_in[3];
    const float* Wv = (const float*)d_in[4];
    const float* Wo = (const float*)d_in[5];
    const float* g1 = (const float*)d_in[6];
    const float* b1 = (const float*)d_in[7];
    const float* g2 = (const float*)d_in[8];
    const float* b2 = (const float*)d_in[9];
    const float* W1 = (const float*)d_in[10];
    const float* W2 = (const float*)d_in[11];
    float* out = (float*)d_out;

    float *pAttn, *pX1, *pBN1, *pMid, *pX2, *pStats;
    cudaGetSymbolAddress((void**)&pAttn, g_attn);
    cudaGetSymbolAddress((void**)&pX1,   g_x1);
    cudaGetSymbolAddress((void**)&pBN1,  g_bn1);
    cudaGetSymbolAddress((void**)&pMid,  g_mid);
    cudaGetSymbolAddress((void**)&pX2,   g_x2);
    cudaGetSymbolAddress((void**)&pStats, g_stats);

    cudaFuncSetAttribute(qkv_gemm_mma, cudaFuncAttributeMaxDynamicSharedMemorySize, GEMM_SMEM);
    cudaFuncSetAttribute(gemm_mma,     cudaFuncAttributeMaxDynamicSharedMemorySize, GEMM_SMEM);

    zero_stats<<<5, 256>>>();
    csr_build<<<NN, 256>>>(A);

    dim3 gQKV(DD / BN, NN / BM, 3);     // (4, 32, 3)
    dim3 g256(DD / BN, NN / BM);        // (4, 32)
    dim3 g512(FFD / BN, NN / BM);       // (8, 32)

    qkv_gemm_mma<<<gQKV, 256, GEMM_SMEM>>>(h, Wq, Wk, Wv);

    colsum_v<<<64, 256>>>();
    attn_sparse<<<NN, 256>>>(pAttn);

    gemm_mma<<<g256, 256, GEMM_SMEM>>>(pAttn, Wo, pX1, DD, DD, 3, h);

    bn_stats<<<64, 256>>>(pX1, pStats + 256, pStats + 512);
    bn_apply<<<NN, 256>>>(pX1, pStats + 256, pStats + 512, g1, b1, pBN1);

    gemm_mma<<<g512, 256, GEMM_SMEM>>>(pBN1, W1, pMid, DD, FFD, 2, nullptr);
    gemm_mma<<<g256, 256, GEMM_SMEM>>>(pMid, W2, pX2, FFD, DD, 3, pBN1);

    bn_stats<<<64, 256>>>(pX2, pStats + 768, pStats + 1024);
    bn_apply<<<NN, 256>>>(pX2, pStats + 768, pStats + 1024, g2, b2, out);
}